// round 4
// baseline (speedup 1.0000x reference)
#include <cuda_runtime.h>
#include <cuda_bf16.h>
#include <mma.h>
#include <math_constants.h>
#include <cstdint>

using namespace nvcuda;

#define Nn 2
#define Ll 2048
#define Hh 8
#define Ee 64
#define Mm 2048
#define HEADS 16
#define NLH (HEADS*Ll)

#define NRM   0.3535533905932738f    // 64^-0.25
#define HNRM2 0.0625f                // 0.5 * NRM^2
#define RATIO 0.022097086912079608f  // 2048^-0.5
#define KEPS  1e-4f
#define EPSZ  1e-6f

// ---------------- scratch ----------------
__device__ float g_Dq[(size_t)HEADS*Ll*Mm];
__device__ float g_Dk[(size_t)HEADS*Ll*Mm];
__device__ float g_rmax[2][NLH];
__device__ float g_diag[2][NLH];
__device__ float g_ksum[HEADS*Mm];
__device__ float g_kvT[(size_t)HEADS*Ee*Mm];  // kv transposed [head][e][m]

__device__ __forceinline__ void atomicMaxF(float* addr, float v) {
    int* ia = (int*)addr;
    int old = *ia;
    while (__int_as_float(old) < v) {
        int assumed = old;
        old = atomicCAS(ia, assumed, __float_as_int(v));
        if (old == assumed) break;
    }
}

__device__ __forceinline__ void split1(float v, __nv_bfloat16& hi, __nv_bfloat16& lo) {
    hi = __float2bfloat16_rn(v);
    lo = __float2bfloat16_rn(v - __bfloat162float(hi));
}
__device__ __forceinline__ void split2pack(float a, float b, uint32_t& hi, uint32_t& lo) {
    __nv_bfloat16 ha, la, hb, lb;
    split1(a, ha, la); split1(b, hb, lb);
    __nv_bfloat162 H = __halves2bfloat162(ha, hb), L = __halves2bfloat162(la, lb);
    hi = *(uint32_t*)&H; lo = *(uint32_t*)&L;
}
__device__ __forceinline__ void split4pack(const float* v, uint2& hi, uint2& lo) {
    split2pack(v[0], v[1], hi.x, lo.x);
    split2pack(v[2], v[3], hi.y, lo.y);
}

typedef wmma::fragment<wmma::matrix_a, 16, 16, 16, __nv_bfloat16, wmma::row_major> FragA;
typedef wmma::fragment<wmma::matrix_b, 16, 16, 16, __nv_bfloat16, wmma::col_major> FragB;
typedef wmma::fragment<wmma::accumulator, 16, 16, 16, float> FragC;

// ================== K0: diag + rowmax init + zero accumulators ==================
__global__ __launch_bounds__(256) void k_init(const float* __restrict__ q,
                                              const float* __restrict__ kk)
{
    int g = blockIdx.x * 256 + threadIdx.x;    // 2,097,152 threads
    g_kvT[g] = 0.0f;                            // exactly HEADS*Ee*Mm elements
    if (g < HEADS*Mm) g_ksum[g] = 0.0f;

    int w = g >> 5, lane = g & 31;
    int which = (w >= NLH) ? 1 : 0;
    int r = which ? (w - NLH) : w;
    int head = r >> 11, l = r & (Ll - 1);
    int n = head >> 3, h = head & 7;
    const float* x = (which ? kk : q) + ((size_t)((n*Ll + l)*Hh + h))*Ee;
    float a = x[lane], b = x[lane + 32];
    float s = a*a + b*b;
    #pragma unroll
    for (int o = 16; o; o >>= 1) s += __shfl_xor_sync(0xffffffffu, s, o);
    if (lane == 0) {
        g_diag[which][r] = HNRM2 * s;
        g_rmax[which][r] = -CUDART_INF_F;
    }
}

// ================== K1: featurize: dash = (x*NRM) @ P^T, raw out + rowmax ==
#define FK_LD 72
#define F_SMEM 73728
__global__ __launch_bounds__(256, 2) void k_feat(const float* __restrict__ X,
                                                 const float* __restrict__ P,
                                                 int which)
{
    extern __shared__ char smem[];
    __nv_bfloat16* Ahi = (__nv_bfloat16*)(smem);
    __nv_bfloat16* Alo = (__nv_bfloat16*)(smem + 18432);
    __nv_bfloat16* Bhi = (__nv_bfloat16*)(smem + 36864);
    __nv_bfloat16* Blo = (__nv_bfloat16*)(smem + 55296);
    float* stage = (float*)smem;

    float* __restrict__ Dash = which ? g_Dk : g_Dq;
    float* __restrict__ rmax = g_rmax[which];

    const int head = blockIdx.z, n = head >> 3, h = head & 7;
    const int l0 = blockIdx.y * 128, m0 = blockIdx.x * 128;
    const int tid = threadIdx.x, wid = tid >> 5, lane = tid & 31;

    {
        int row = tid >> 1;
        int colb = (tid & 1) * 32;
        const float* srcA = X + ((size_t)((n*Ll + l0 + row)*Hh + h))*Ee + colb;
        const float* srcB = P + (size_t)(m0 + row)*Ee + colb;
        #pragma unroll
        for (int j = 0; j < 8; j++) {
            float4 va = *(const float4*)(srcA + j*4);
            float av[4] = {va.x*NRM, va.y*NRM, va.z*NRM, va.w*NRM};
            uint2 hi, lo; split4pack(av, hi, lo);
            int off = row*FK_LD + colb + j*4;
            *(uint2*)&Ahi[off] = hi; *(uint2*)&Alo[off] = lo;
            float4 vb = *(const float4*)(srcB + j*4);
            float bv[4] = {vb.x, vb.y, vb.z, vb.w};
            split4pack(bv, hi, lo);
            *(uint2*)&Bhi[off] = hi; *(uint2*)&Blo[off] = lo;
        }
    }
    __syncthreads();

    const int warp_l = (wid & 3) * 32, warp_m = (wid >> 2) * 64;
    FragC c[2][4];
    #pragma unroll
    for (int i = 0; i < 2; i++)
        #pragma unroll
        for (int j = 0; j < 4; j++) wmma::fill_fragment(c[i][j], 0.0f);

    #pragma unroll
    for (int k = 0; k < 4; k++) {
        FragA ahi[2], alo[2];
        #pragma unroll
        for (int i = 0; i < 2; i++) {
            wmma::load_matrix_sync(ahi[i], Ahi + (warp_l + i*16)*FK_LD + k*16, FK_LD);
            wmma::load_matrix_sync(alo[i], Alo + (warp_l + i*16)*FK_LD + k*16, FK_LD);
        }
        #pragma unroll
        for (int j = 0; j < 4; j++) {
            FragB bhi, blo;
            wmma::load_matrix_sync(bhi, Bhi + k*16 + (warp_m + j*16)*FK_LD, FK_LD);
            wmma::load_matrix_sync(blo, Blo + k*16 + (warp_m + j*16)*FK_LD, FK_LD);
            #pragma unroll
            for (int i = 0; i < 2; i++) {
                wmma::mma_sync(c[i][j], ahi[i], bhi, c[i][j]);
                wmma::mma_sync(c[i][j], ahi[i], blo, c[i][j]);
                wmma::mma_sync(c[i][j], alo[i], bhi, c[i][j]);
            }
        }
    }
    __syncthreads();
    #pragma unroll
    for (int i = 0; i < 2; i++)
        #pragma unroll
        for (int j = 0; j < 4; j++)
            wmma::store_matrix_sync(stage + (warp_l + i*16)*132 + warp_m + j*16,
                                    c[i][j], 132, wmma::mem_row_major);
    __syncthreads();

    #pragma unroll
    for (int r = 0; r < 16; r++) {
        int row = wid * 16 + r;
        float4 v = *(const float4*)&stage[row*132 + lane*4];
        *(float4*)(Dash + (size_t)(head*Ll + l0 + row)*Mm + m0 + lane*4) = v;
        float rm = fmaxf(fmaxf(v.x, v.y), fmaxf(v.z, v.w));
        #pragma unroll
        for (int o = 16; o; o >>= 1) rm = fmaxf(rm, __shfl_xor_sync(0xffffffffu, rm, o));
        if (lane == 0) atomicMaxF(&rmax[head*Ll + l0 + row], rm);
    }
}

// ================== K2: kv = k'^T @ v  (pipelined, s-split 2-way) ==========
// block: (m-tile 128, s-half 1024, head). chunk=32 s. double-buffered smem.
#define KV_BUF 30720           // per stage: Ahi 10240 | Alo 10240 | Bhi 5120 | Blo 5120
#define KV_SMEM 65536          // 2 bufs + SUB[1024]
__global__ __launch_bounds__(256, 2) void k_kv(const float* __restrict__ V)
{
    extern __shared__ char smem[];
    float* SUB = (float*)(smem + 61440);

    const int head = blockIdx.z, n = head >> 3, h = head & 7;
    const int m0 = blockIdx.x * 128;
    const int sbase = blockIdx.y * 1024;
    const int tid = threadIdx.x, wid = tid >> 5;

    for (int i = tid; i < 1024; i += 256) {
        int gr = head*Ll + sbase + i;
        SUB[i] = g_diag[1][gr] + g_rmax[1][gr];
    }

    const int mA = tid & 127, sgA = (tid >> 7) * 16;
    const int eB = tid & 63,  sgB = (tid >> 6) * 8;
    const int warp_m = (wid & 3) * 32, warp_e = (wid >> 2) * 32;

    FragC c[2][2];
    #pragma unroll
    for (int i = 0; i < 2; i++)
        #pragma unroll
        for (int j = 0; j < 2; j++) wmma::fill_fragment(c[i][j], 0.0f);

    float aR[16], bR[8], ksp = 0.0f;
    // preload chunk 0
    {
        const float* dk = g_Dk + (size_t)(head*Ll + sbase + sgA)*Mm + m0 + mA;
        #pragma unroll
        for (int i = 0; i < 16; i++) aR[i] = dk[(size_t)i * Mm];
        const float* vp = V + ((size_t)((n*Ll + sbase + sgB)*Hh + h))*Ee + eB;
        #pragma unroll
        for (int i = 0; i < 8; i++) bR[i] = vp[(size_t)i * (Hh*Ee)];
    }
    __syncthreads();

    for (int t = 0; t < 32; t++) {
        char* buf = smem + (t & 1) * KV_BUF;
        __nv_bfloat16* Ah = (__nv_bfloat16*)buf;
        __nv_bfloat16* Al = (__nv_bfloat16*)(buf + 10240);
        __nv_bfloat16* Bh = (__nv_bfloat16*)(buf + 20480);
        __nv_bfloat16* Bl = (__nv_bfloat16*)(buf + 25600);

        // STS A with exp + ksum
        #pragma unroll
        for (int i = 0; i < 16; i += 2) {
            float k0 = RATIO * (__expf(aR[i]   - SUB[t*32 + sgA + i])   + KEPS);
            float k1 = RATIO * (__expf(aR[i+1] - SUB[t*32 + sgA + i+1]) + KEPS);
            ksp += k0 + k1;
            uint32_t hi, lo; split2pack(k0, k1, hi, lo);
            *(uint32_t*)&Ah[mA*40 + sgA + i] = hi;
            *(uint32_t*)&Al[mA*40 + sgA + i] = lo;
        }
        // STS B
        #pragma unroll
        for (int i = 0; i < 8; i += 2) {
            uint32_t hi, lo; split2pack(bR[i], bR[i+1], hi, lo);
            *(uint32_t*)&Bh[eB*40 + sgB + i] = hi;
            *(uint32_t*)&Bl[eB*40 + sgB + i] = lo;
        }
        __syncthreads();

        if (t < 31) {  // lead-load next chunk, overlapped with MMA
            const int s1 = sbase + (t+1)*32;
            const float* dk = g_Dk + (size_t)(head*Ll + s1 + sgA)*Mm + m0 + mA;
            #pragma unroll
            for (int i = 0; i < 16; i++) aR[i] = dk[(size_t)i * Mm];
            const float* vp = V + ((size_t)((n*Ll + s1 + sgB)*Hh + h))*Ee + eB;
            #pragma unroll
            for (int i = 0; i < 8; i++) bR[i] = vp[(size_t)i * (Hh*Ee)];
        }

        #pragma unroll
        for (int k = 0; k < 2; k++) {
            FragA ahi[2], alo[2];
            #pragma unroll
            for (int i = 0; i < 2; i++) {
                wmma::load_matrix_sync(ahi[i], Ah + (warp_m + i*16)*40 + k*16, 40);
                wmma::load_matrix_sync(alo[i], Al + (warp_m + i*16)*40 + k*16, 40);
            }
            #pragma unroll
            for (int j = 0; j < 2; j++) {
                FragB bhi, blo;
                wmma::load_matrix_sync(bhi, Bh + (warp_e + j*16)*40 + k*16, 40);
                wmma::load_matrix_sync(blo, Bl + (warp_e + j*16)*40 + k*16, 40);
                #pragma unroll
                for (int i = 0; i < 2; i++) {
                    wmma::mma_sync(c[i][j], ahi[i], bhi, c[i][j]);
                    wmma::mma_sync(c[i][j], ahi[i], blo, c[i][j]);
                    wmma::mma_sync(c[i][j], alo[i], bhi, c[i][j]);
                }
            }
        }
    }

    atomicAdd(&g_ksum[head*Mm + m0 + mA], ksp);

    __syncthreads();     // stage overlaps buffer 1 — all MMA reads must finish
    float* stage = (float*)smem;   // col-major [e][m], ld 132
    #pragma unroll
    for (int i = 0; i < 2; i++)
        #pragma unroll
        for (int j = 0; j < 2; j++)
            wmma::store_matrix_sync(stage + (warp_m + i*16) + (warp_e + j*16)*132,
                                    c[i][j], 132, wmma::mem_col_major);
    __syncthreads();
    {
        int e = tid >> 2, mo = (tid & 3) * 32;
        float* dst = g_kvT + (size_t)(head*Ee + e)*Mm + m0 + mo;
        const float* src = stage + e*132 + mo;
        #pragma unroll
        for (int j = 0; j < 32; j++) atomicAdd(dst + j, src[j]);
    }
}

// ================== K3: out = z * q' @ kv^T (pipelined, l-tile 64) =========
#define O_BUF 20480            // per stage: Ahi 5120 | Alo 5120 | Bhi 5120 | Blo 5120
#define O_SMEM 49664           // 2 bufs + KS[2048] + SUBL[64] + DEN[64]
__global__ __launch_bounds__(256, 2) void k_out(float* __restrict__ out)
{
    extern __shared__ char smem[];
    float* KS   = (float*)(smem + 40960);
    float* SUBL = (float*)(smem + 49152);
    float* DEN  = (float*)(smem + 49408);

    const int head = blockIdx.y, n = head >> 3, h = head & 7;
    const int l0 = blockIdx.x * 64;
    const int tid = threadIdx.x, wid = tid >> 5;

    for (int i = tid; i < 2048; i += 256) KS[i] = g_ksum[head*Mm + i];
    if (tid < 64) {
        int gr = head*Ll + l0 + tid;
        SUBL[tid] = g_diag[0][gr] + g_rmax[0][gr];
        DEN[tid] = 0.0f;
    }

    const int lA = tid >> 2, mcA = (tid & 3) * 8;
    const int eB = tid >> 2, mcB = (tid & 3) * 8;
    const int warp_l = (wid & 3) * 16, warp_e = (wid >> 2) * 32;

    FragC c[2];
    wmma::fill_fragment(c[0], 0.0f);
    wmma::fill_fragment(c[1], 0.0f);

    float aR[8], bR[8], den_acc = 0.0f;
    const size_t grA = (size_t)(head*Ll + l0 + lA);
    // preload chunk 0
    {
        const float* dq = g_Dq + grA*Mm + mcA;
        #pragma unroll
        for (int i = 0; i < 8; i++) aR[i] = dq[i];
        const float* kv = g_kvT + (size_t)(head*Ee + eB)*Mm + mcB;
        #pragma unroll
        for (int i = 0; i < 8; i++) bR[i] = kv[i];
    }
    __syncthreads();
    const float subA = SUBL[lA];

    for (int t = 0; t < 64; t++) {
        char* buf = smem + (t & 1) * O_BUF;
        __nv_bfloat16* Ah = (__nv_bfloat16*)buf;
        __nv_bfloat16* Al = (__nv_bfloat16*)(buf + 5120);
        __nv_bfloat16* Bh = (__nv_bfloat16*)(buf + 10240);
        __nv_bfloat16* Bl = (__nv_bfloat16*)(buf + 15360);

        #pragma unroll
        for (int i = 0; i < 8; i += 2) {
            float q0 = RATIO * (__expf(aR[i]   - subA) + KEPS);
            float q1 = RATIO * (__expf(aR[i+1] - subA) + KEPS);
            den_acc += q0 * KS[t*32 + mcA + i] + q1 * KS[t*32 + mcA + i + 1];
            uint32_t hi, lo; split2pack(q0, q1, hi, lo);
            *(uint32_t*)&Ah[lA*40 + mcA + i] = hi;
            *(uint32_t*)&Al[lA*40 + mcA + i] = lo;
        }
        #pragma unroll
        for (int i = 0; i < 8; i += 2) {
            uint32_t hi, lo; split2pack(bR[i], bR[i+1], hi, lo);
            *(uint32_t*)&Bh[eB*40 + mcB + i] = hi;
            *(uint32_t*)&Bl[eB*40 + mcB + i] = lo;
        }
        __syncthreads();

        if (t < 63) {
            const int m1 = (t+1) * 32;
            const float* dq = g_Dq + grA*Mm + m1 + mcA;
            #pragma unroll
            for (int i = 0; i < 8; i++) aR[i] = dq[i];
            const float* kv = g_kvT + (size_t)(head*Ee + eB)*Mm + m1 + mcB;
            #pragma unroll
            for (int i = 0; i < 8; i++) bR[i] = kv[i];
        }

        #pragma unroll
        for (int k = 0; k < 2; k++) {
            FragA ahi, alo;
            wmma::load_matrix_sync(ahi, Ah + warp_l*40 + k*16, 40);
            wmma::load_matrix_sync(alo, Al + warp_l*40 + k*16, 40);
            #pragma unroll
            for (int j = 0; j < 2; j++) {
                FragB bhi, blo;
                wmma::load_matrix_sync(bhi, Bh + (warp_e + j*16)*40 + k*16, 40);
                wmma::load_matrix_sync(blo, Bl + (warp_e + j*16)*40 + k*16, 40);
                wmma::mma_sync(c[j], ahi, bhi, c[j]);
                wmma::mma_sync(c[j], ahi, blo, c[j]);
                wmma::mma_sync(c[j], alo, bhi, c[j]);
            }
        }
    }

    atomicAdd(&DEN[lA], den_acc);
    __syncthreads();    // last MMA read buf1 (20480..); stage (0..17408) disjoint,
                        // but epilogue reads others' stage rows + DEN — sync after stores
    float* stage = (float*)smem;    // row-major [l][e], ld 68
    #pragma unroll
    for (int j = 0; j < 2; j++)
        wmma::store_matrix_sync(stage + warp_l*68 + warp_e + j*16, c[j], 68,
                                wmma::mem_row_major);
    __syncthreads();
    {
        int l = tid >> 2, ec = (tid & 3) * 16;
        float z = 1.0f / (DEN[l] + EPSZ);
        float* dst = out + ((size_t)((n*Ll + l0 + l)*Hh + h))*Ee + ec;
        const float* src = stage + l*68 + ec;
        #pragma unroll
        for (int j = 0; j < 4; j++) {
            float4 v = *(const float4*)(src + j*4);
            *(float4*)(dst + j*4) = make_float4(v.x*z, v.y*z, v.z*z, v.w*z);
        }
    }
}

// ================== launch ==================
extern "C" void kernel_launch(void* const* d_in, const int* in_sizes, int n_in,
                              void* d_out, int out_size)
{
    const float* q = (const float*)d_in[0];
    const float* k = (const float*)d_in[1];
    const float* v = (const float*)d_in[2];
    const float* p = (const float*)d_in[3];
    float* out = (float*)d_out;

    cudaFuncSetAttribute(k_feat, cudaFuncAttributeMaxDynamicSharedMemorySize, F_SMEM);
    cudaFuncSetAttribute(k_kv,   cudaFuncAttributeMaxDynamicSharedMemorySize, KV_SMEM);
    cudaFuncSetAttribute(k_out,  cudaFuncAttributeMaxDynamicSharedMemorySize, O_SMEM);

    k_init<<<8192, 256>>>(q, k);
    k_feat<<<dim3(16, 16, HEADS), 256, F_SMEM>>>(q, p, 0);
    k_feat<<<dim3(16, 16, HEADS), 256, F_SMEM>>>(k, p, 1);
    k_kv<<<dim3(16, 2, HEADS), 256, KV_SMEM>>>(v);
    k_out<<<dim3(32, HEADS), 256, O_SMEM>>>(out);
}

// round 5
// speedup vs baseline: 1.1484x; 1.1484x over previous
#include <cuda_runtime.h>
#include <cuda_bf16.h>
#include <mma.h>
#include <math_constants.h>
#include <cstdint>

using namespace nvcuda;

#define Nn 2
#define Ll 2048
#define Hh 8
#define Ee 64
#define Mm 2048
#define HEADS 16
#define NLH (HEADS*Ll)

#define NRM   0.3535533905932738f
#define HNRM2 0.0625f
#define RATIO 0.022097086912079608f
#define KEPS  1e-4f
#define EPSZ  1e-6f

// ---------------- scratch ----------------
__device__ float g_Dq[(size_t)HEADS*Ll*Mm];
__device__ float g_Dk[(size_t)HEADS*Ll*Mm];
__device__ float g_rmax[2][NLH];
__device__ float g_diag[2][NLH];
__device__ float g_ksum[HEADS*Mm];
__device__ float g_kvT[(size_t)HEADS*Ee*Mm];  // [head][e][m]

__device__ __forceinline__ void atomicMaxF(float* addr, float v) {
    int* ia = (int*)addr;
    int old = *ia;
    while (__int_as_float(old) < v) {
        int assumed = old;
        old = atomicCAS(ia, assumed, __float_as_int(v));
        if (old == assumed) break;
    }
}

__device__ __forceinline__ void split1(float v, __nv_bfloat16& hi, __nv_bfloat16& lo) {
    hi = __float2bfloat16_rn(v);
    lo = __float2bfloat16_rn(v - __bfloat162float(hi));
}
__device__ __forceinline__ void split2pack(float a, float b, uint32_t& hi, uint32_t& lo) {
    __nv_bfloat16 ha, la, hb, lb;
    split1(a, ha, la); split1(b, hb, lb);
    __nv_bfloat162 H = __halves2bfloat162(ha, hb), L = __halves2bfloat162(la, lb);
    hi = *(uint32_t*)&H; lo = *(uint32_t*)&L;
}
__device__ __forceinline__ void split4pack(const float* v, uint2& hi, uint2& lo) {
    split2pack(v[0], v[1], hi.x, lo.x);
    split2pack(v[2], v[3], hi.y, lo.y);
}

__device__ __forceinline__ uint32_t smem_u32(const void* p) {
    uint32_t a;
    asm("{ .reg .u64 t; cvta.to.shared.u64 t, %1; cvt.u32.u64 %0, t; }" : "=r"(a) : "l"(p));
    return a;
}
__device__ __forceinline__ void cp16(uint32_t s, const void* g) {
    asm volatile("cp.async.cg.shared.global [%0], [%1], 16;" :: "r"(s), "l"(g));
}
#define CP_COMMIT() asm volatile("cp.async.commit_group;" ::: "memory")
#define CP_WAIT1()  asm volatile("cp.async.wait_group 1;" ::: "memory")
#define CP_WAIT0()  asm volatile("cp.async.wait_group 0;" ::: "memory")

typedef wmma::fragment<wmma::matrix_a, 16, 16, 16, __nv_bfloat16, wmma::row_major> FragA;
typedef wmma::fragment<wmma::matrix_b, 16, 16, 16, __nv_bfloat16, wmma::col_major> FragB;
typedef wmma::fragment<wmma::accumulator, 16, 16, 16, float> FragC;

// ================== K0: diag + rowmax init ==================
__global__ __launch_bounds__(256) void k_init(const float* __restrict__ q,
                                              const float* __restrict__ kk)
{
    int g = blockIdx.x * 256 + threadIdx.x;
    int w = g >> 5, lane = g & 31;
    int which = (w >= NLH) ? 1 : 0;
    int r = which ? (w - NLH) : w;
    int head = r >> 11, l = r & (Ll - 1);
    int n = head >> 3, h = head & 7;
    const float* x = (which ? kk : q) + ((size_t)((n*Ll + l)*Hh + h))*Ee;
    float a = x[lane], b = x[lane + 32];
    float s = a*a + b*b;
    #pragma unroll
    for (int o = 16; o; o >>= 1) s += __shfl_xor_sync(0xffffffffu, s, o);
    if (lane == 0) {
        g_diag[which][r] = HNRM2 * s;
        g_rmax[which][r] = -CUDART_INF_F;
    }
}

// ================== K1: featurize (merged q+k launch) ==================
#define FK_LD 72
#define F_SMEM 73728
__global__ __launch_bounds__(256, 2) void k_feat(const float* __restrict__ Q,
                                                 const float* __restrict__ K,
                                                 const float* __restrict__ P)
{
    extern __shared__ char smem[];
    __nv_bfloat16* Ahi = (__nv_bfloat16*)(smem);
    __nv_bfloat16* Alo = (__nv_bfloat16*)(smem + 18432);
    __nv_bfloat16* Bhi = (__nv_bfloat16*)(smem + 36864);
    __nv_bfloat16* Blo = (__nv_bfloat16*)(smem + 55296);
    float* stage = (float*)smem;

    const int which = blockIdx.z >> 4;
    const int head = blockIdx.z & 15, n = head >> 3, h = head & 7;
    const float* X = which ? K : Q;
    float* __restrict__ Dash = which ? g_Dk : g_Dq;
    float* __restrict__ rmax = g_rmax[which];

    const int l0 = blockIdx.y * 128, m0 = blockIdx.x * 128;
    const int tid = threadIdx.x, wid = tid >> 5, lane = tid & 31;

    {
        int row = tid >> 1;
        int colb = (tid & 1) * 32;
        const float* srcA = X + ((size_t)((n*Ll + l0 + row)*Hh + h))*Ee + colb;
        const float* srcB = P + (size_t)(m0 + row)*Ee + colb;
        #pragma unroll
        for (int j = 0; j < 8; j++) {
            float4 va = *(const float4*)(srcA + j*4);
            float av[4] = {va.x*NRM, va.y*NRM, va.z*NRM, va.w*NRM};
            uint2 hi, lo; split4pack(av, hi, lo);
            int off = row*FK_LD + colb + j*4;
            *(uint2*)&Ahi[off] = hi; *(uint2*)&Alo[off] = lo;
            float4 vb = *(const float4*)(srcB + j*4);
            float bv[4] = {vb.x, vb.y, vb.z, vb.w};
            split4pack(bv, hi, lo);
            *(uint2*)&Bhi[off] = hi; *(uint2*)&Blo[off] = lo;
        }
    }
    __syncthreads();

    const int warp_l = (wid & 3) * 32, warp_m = (wid >> 2) * 64;
    FragC c[2][4];
    #pragma unroll
    for (int i = 0; i < 2; i++)
        #pragma unroll
        for (int j = 0; j < 4; j++) wmma::fill_fragment(c[i][j], 0.0f);

    #pragma unroll
    for (int k = 0; k < 4; k++) {
        FragA ahi[2], alo[2];
        #pragma unroll
        for (int i = 0; i < 2; i++) {
            wmma::load_matrix_sync(ahi[i], Ahi + (warp_l + i*16)*FK_LD + k*16, FK_LD);
            wmma::load_matrix_sync(alo[i], Alo + (warp_l + i*16)*FK_LD + k*16, FK_LD);
        }
        #pragma unroll
        for (int j = 0; j < 4; j++) {
            FragB bhi, blo;
            wmma::load_matrix_sync(bhi, Bhi + k*16 + (warp_m + j*16)*FK_LD, FK_LD);
            wmma::load_matrix_sync(blo, Blo + k*16 + (warp_m + j*16)*FK_LD, FK_LD);
            #pragma unroll
            for (int i = 0; i < 2; i++) {
                wmma::mma_sync(c[i][j], ahi[i], bhi, c[i][j]);
                wmma::mma_sync(c[i][j], ahi[i], blo, c[i][j]);
                wmma::mma_sync(c[i][j], alo[i], bhi, c[i][j]);
            }
        }
    }
    __syncthreads();
    #pragma unroll
    for (int i = 0; i < 2; i++)
        #pragma unroll
        for (int j = 0; j < 4; j++)
            wmma::store_matrix_sync(stage + (warp_l + i*16)*132 + warp_m + j*16,
                                    c[i][j], 132, wmma::mem_row_major);
    __syncthreads();

    #pragma unroll
    for (int r = 0; r < 16; r++) {
        int row = wid * 16 + r;
        float4 v = *(const float4*)&stage[row*132 + lane*4];
        *(float4*)(Dash + (size_t)(head*Ll + l0 + row)*Mm + m0 + lane*4) = v;
        float rm = fmaxf(fmaxf(v.x, v.y), fmaxf(v.z, v.w));
        #pragma unroll
        for (int o = 16; o; o >>= 1) rm = fmaxf(rm, __shfl_xor_sync(0xffffffffu, rm, o));
        if (lane == 0) atomicMaxF(&rmax[head*Ll + l0 + row], rm);
    }
}

// ================== K2: kv = k'^T @ v  (cp.async pipelined) ==================
// CTA = (m-tile 128, head). 64 chunks of 32 s.
// smem: rawK 2x16K | rawV 2x8K | Ah/Al 10240x2 | Bh/Bl 5120x2 | SUB 8K | KS 512
#define KV_RAWV   32768
#define KV_AH     49152
#define KV_AL     59392
#define KV_BH     69632
#define KV_BL     74752
#define KV_SUB    79872
#define KV_KS     88064
#define KV_SMEM   88576
__global__ __launch_bounds__(256, 2) void k_kv(const float* __restrict__ V)
{
    extern __shared__ char smem[];
    const uint32_t sb = smem_u32(smem);
    __nv_bfloat16* Ah = (__nv_bfloat16*)(smem + KV_AH);
    __nv_bfloat16* Al = (__nv_bfloat16*)(smem + KV_AL);
    __nv_bfloat16* Bh = (__nv_bfloat16*)(smem + KV_BH);
    __nv_bfloat16* Bl = (__nv_bfloat16*)(smem + KV_BL);
    float* SUB = (float*)(smem + KV_SUB);
    float* KS  = (float*)(smem + KV_KS);

    const int head = blockIdx.y, n = head >> 3, h = head & 7;
    const int m0 = blockIdx.x * 128;
    const int tid = threadIdx.x, wid = tid >> 5;

    // prologue fills for chunks 0,1
    #pragma unroll
    for (int t = 0; t < 2; t++) {
        const float* srcK = g_Dk + (size_t)(head*Ll + t*32)*Mm + m0;
        uint32_t dK = sb + t*16384;
        #pragma unroll
        for (int j = 0; j < 4; j++) {
            int g = tid + j*256, row = g >> 5, col = (g & 31)*4;
            cp16(dK + (row*128 + col)*4, srcK + (size_t)row*Mm + col);
        }
        uint32_t dV = sb + KV_RAWV + t*8192;
        #pragma unroll
        for (int j = 0; j < 2; j++) {
            int g = tid + j*256, row = g >> 4, col = (g & 15)*4;
            cp16(dV + (row*64 + col)*4,
                 V + ((size_t)((n*Ll + t*32 + row)*Hh + h))*Ee + col);
        }
        CP_COMMIT();
    }

    for (int i = tid; i < 2048; i += 256) {
        int gr = head*Ll + i;
        SUB[i] = g_diag[1][gr] + g_rmax[1][gr];
    }
    if (tid < 128) KS[tid] = 0.0f;

    const int mA = tid & 127, sgA = (tid >> 7) * 16;
    const int eB = tid & 63,  sgB = (tid >> 6) * 8;
    const int warp_m = (wid & 3) * 32, warp_e = (wid >> 2) * 32;

    FragC c[2][2];
    #pragma unroll
    for (int i = 0; i < 2; i++)
        #pragma unroll
        for (int j = 0; j < 2; j++) wmma::fill_fragment(c[i][j], 0.0f);

    float ksp = 0.0f;

    for (int t = 0; t < 64; t++) {
        if (t < 63) { CP_WAIT1(); } else { CP_WAIT0(); }
        __syncthreads();   // raw(t) visible; MMA(t-1) done -> operands writable

        const float* RK = (const float*)(smem + (t & 1)*16384);
        const float* RV = (const float*)(smem + KV_RAWV + (t & 1)*8192);

        #pragma unroll
        for (int i = 0; i < 16; i += 2) {
            float f0 = RK[(sgA + i)*128 + mA];
            float f1 = RK[(sgA + i + 1)*128 + mA];
            float k0 = RATIO * (__expf(f0 - SUB[t*32 + sgA + i])     + KEPS);
            float k1 = RATIO * (__expf(f1 - SUB[t*32 + sgA + i + 1]) + KEPS);
            ksp += k0 + k1;
            uint32_t hi, lo; split2pack(k0, k1, hi, lo);
            *(uint32_t*)&Ah[mA*40 + sgA + i] = hi;
            *(uint32_t*)&Al[mA*40 + sgA + i] = lo;
        }
        #pragma unroll
        for (int i = 0; i < 8; i += 2) {
            float v0 = RV[(sgB + i)*64 + eB];
            float v1 = RV[(sgB + i + 1)*64 + eB];
            uint32_t hi, lo; split2pack(v0, v1, hi, lo);
            *(uint32_t*)&Bh[eB*40 + sgB + i] = hi;
            *(uint32_t*)&Bl[eB*40 + sgB + i] = lo;
        }
        __syncthreads();   // operands ready; raw(t) fully consumed

        if (t + 2 < 64) {  // refill buffer (t&1) for chunk t+2
            const int s1 = (t + 2) * 32;
            const float* srcK = g_Dk + (size_t)(head*Ll + s1)*Mm + m0;
            uint32_t dK = sb + (t & 1)*16384;
            #pragma unroll
            for (int j = 0; j < 4; j++) {
                int g = tid + j*256, row = g >> 5, col = (g & 31)*4;
                cp16(dK + (row*128 + col)*4, srcK + (size_t)row*Mm + col);
            }
            uint32_t dV = sb + KV_RAWV + (t & 1)*8192;
            #pragma unroll
            for (int j = 0; j < 2; j++) {
                int g = tid + j*256, row = g >> 4, col = (g & 15)*4;
                cp16(dV + (row*64 + col)*4,
                     V + ((size_t)((n*Ll + s1 + row)*Hh + h))*Ee + col);
            }
            CP_COMMIT();
        }

        #pragma unroll
        for (int k = 0; k < 2; k++) {
            FragA ahi[2], alo[2];
            #pragma unroll
            for (int i = 0; i < 2; i++) {
                wmma::load_matrix_sync(ahi[i], Ah + (warp_m + i*16)*40 + k*16, 40);
                wmma::load_matrix_sync(alo[i], Al + (warp_m + i*16)*40 + k*16, 40);
            }
            #pragma unroll
            for (int j = 0; j < 2; j++) {
                FragB bhi, blo;
                wmma::load_matrix_sync(bhi, Bh + (warp_e + j*16)*40 + k*16, 40);
                wmma::load_matrix_sync(blo, Bl + (warp_e + j*16)*40 + k*16, 40);
                #pragma unroll
                for (int i = 0; i < 2; i++) {
                    wmma::mma_sync(c[i][j], ahi[i], bhi, c[i][j]);
                    wmma::mma_sync(c[i][j], ahi[i], blo, c[i][j]);
                    wmma::mma_sync(c[i][j], alo[i], bhi, c[i][j]);
                }
            }
        }
    }

    atomicAdd(&KS[mA], ksp);
    __syncthreads();
    float* stage = (float*)smem;   // col-major [e][m], ld 132
    #pragma unroll
    for (int i = 0; i < 2; i++)
        #pragma unroll
        for (int j = 0; j < 2; j++)
            wmma::store_matrix_sync(stage + (warp_m + i*16) + (warp_e + j*16)*132,
                                    c[i][j], 132, wmma::mem_col_major);
    __syncthreads();
    if (tid < 128) g_ksum[head*Mm + m0 + tid] = KS[tid];
    {
        int e = tid >> 2, mo = (tid & 3) * 32;
        float* dst = g_kvT + (size_t)(head*Ee + e)*Mm + m0 + mo;
        const float* src = stage + e*132 + mo;
        #pragma unroll
        for (int j = 0; j < 8; j++)
            *(float4*)(dst + j*4) = *(const float4*)(src + j*4);
    }
}

// ================== K3: out = z * q' @ kv^T (cp.async pipelined) =========
// CTA = (l-tile 128, head). 64 chunks of 32 m.
// smem: rawQ 2x18432 | rawKV 2x9216 | Ah/Al | Bh/Bl | KS 8K | SUBL | DEN
#define O_RAWKV  36864
#define O_AH     55296
#define O_AL     65536
#define O_BH     75776
#define O_BL     80896
#define O_KS     86016
#define O_SUBL   94208
#define O_DEN    94720
#define O_SMEM   95232
__global__ __launch_bounds__(256, 2) void k_out(float* __restrict__ out)
{
    extern __shared__ char smem[];
    const uint32_t sb = smem_u32(smem);
    __nv_bfloat16* Ah = (__nv_bfloat16*)(smem + O_AH);
    __nv_bfloat16* Al = (__nv_bfloat16*)(smem + O_AL);
    __nv_bfloat16* Bh = (__nv_bfloat16*)(smem + O_BH);
    __nv_bfloat16* Bl = (__nv_bfloat16*)(smem + O_BL);
    float* KS   = (float*)(smem + O_KS);
    float* SUBL = (float*)(smem + O_SUBL);
    float* DEN  = (float*)(smem + O_DEN);

    const int head = blockIdx.y, n = head >> 3, h = head & 7;
    const int l0 = blockIdx.x * 128;
    const int tid = threadIdx.x, wid = tid >> 5;

    // prologue fills for chunks 0,1
    #pragma unroll
    for (int t = 0; t < 2; t++) {
        const float* srcQ = g_Dq + (size_t)(head*Ll + l0)*Mm + t*32;
        uint32_t dQ = sb + t*18432;
        #pragma unroll
        for (int j = 0; j < 4; j++) {
            int g = tid + j*256, l = g >> 3, col = (g & 7)*4;
            cp16(dQ + (l*36 + col)*4, srcQ + (size_t)l*Mm + col);
        }
        const float* srcB = g_kvT + (size_t)(head*Ee)*Mm + t*32;
        uint32_t dB = sb + O_RAWKV + t*9216;
        #pragma unroll
        for (int j = 0; j < 2; j++) {
            int g = tid + j*256, e = g >> 3, col = (g & 7)*4;
            cp16(dB + (e*36 + col)*4, srcB + (size_t)e*Mm + col);
        }
        CP_COMMIT();
    }

    for (int i = tid; i < 2048; i += 256) KS[i] = g_ksum[head*Mm + i];
    if (tid < 128) {
        int gr = head*Ll + l0 + tid;
        SUBL[tid] = g_diag[0][gr] + g_rmax[0][gr];
        DEN[tid] = 0.0f;
    }

    const int m2 = (tid & 15) * 2, lg = (tid >> 4) * 8;     // A transform
    const int mB = tid & 31, eg = (tid >> 5) * 8;            // B transform
    const int warp_l = (wid & 3) * 32, warp_e = (wid >> 2) * 32;

    FragC c[2][2];
    #pragma unroll
    for (int i = 0; i < 2; i++)
        #pragma unroll
        for (int j = 0; j < 2; j++) wmma::fill_fragment(c[i][j], 0.0f);

    float den[8];
    #pragma unroll
    for (int i = 0; i < 8; i++) den[i] = 0.0f;

    for (int t = 0; t < 64; t++) {
        if (t < 63) { CP_WAIT1(); } else { CP_WAIT0(); }
        __syncthreads();

        const float* RQ = (const float*)(smem + (t & 1)*18432);
        const float* RB = (const float*)(smem + O_RAWKV + (t & 1)*9216);

        #pragma unroll
        for (int i = 0; i < 8; i++) {
            int l = lg + i;
            float2 f = *(const float2*)(RQ + l*36 + m2);
            float sub = SUBL[l];
            float q0 = RATIO * (__expf(f.x - sub) + KEPS);
            float q1 = RATIO * (__expf(f.y - sub) + KEPS);
            den[i] += q0 * KS[t*32 + m2] + q1 * KS[t*32 + m2 + 1];
            uint32_t hi, lo; split2pack(q0, q1, hi, lo);
            *(uint32_t*)&Ah[l*40 + m2] = hi;
            *(uint32_t*)&Al[l*40 + m2] = lo;
        }
        #pragma unroll
        for (int i = 0; i < 8; i++) {
            int e = eg + i;
            float v = RB[e*36 + mB];
            __nv_bfloat16 hb, lb; split1(v, hb, lb);
            Bh[e*40 + mB] = hb;
            Bl[e*40 + mB] = lb;
        }
        __syncthreads();

        if (t + 2 < 64) {
            const int m1 = (t + 2) * 32;
            const float* srcQ = g_Dq + (size_t)(head*Ll + l0)*Mm + m1;
            uint32_t dQ = sb + (t & 1)*18432;
            #pragma unroll
            for (int j = 0; j < 4; j++) {
                int g = tid + j*256, l = g >> 3, col = (g & 7)*4;
                cp16(dQ + (l*36 + col)*4, srcQ + (size_t)l*Mm + col);
            }
            const float* srcB = g_kvT + (size_t)(head*Ee)*Mm + m1;
            uint32_t dB = sb + O_RAWKV + (t & 1)*9216;
            #pragma unroll
            for (int j = 0; j < 2; j++) {
                int g = tid + j*256, e = g >> 3, col = (g & 7)*4;
                cp16(dB + (e*36 + col)*4, srcB + (size_t)e*Mm + col);
            }
            CP_COMMIT();
        }

        #pragma unroll
        for (int k = 0; k < 2; k++) {
            FragA ahi[2], alo[2];
            #pragma unroll
            for (int i = 0; i < 2; i++) {
                wmma::load_matrix_sync(ahi[i], Ah + (warp_l + i*16)*40 + k*16, 40);
                wmma::load_matrix_sync(alo[i], Al + (warp_l + i*16)*40 + k*16, 40);
            }
            #pragma unroll
            for (int j = 0; j < 2; j++) {
                FragB bhi, blo;
                wmma::load_matrix_sync(bhi, Bh + (warp_e + j*16)*40 + k*16, 40);
                wmma::load_matrix_sync(blo, Bl + (warp_e + j*16)*40 + k*16, 40);
                #pragma unroll
                for (int i = 0; i < 2; i++) {
                    wmma::mma_sync(c[i][j], ahi[i], bhi, c[i][j]);
                    wmma::mma_sync(c[i][j], ahi[i], blo, c[i][j]);
                    wmma::mma_sync(c[i][j], alo[i], bhi, c[i][j]);
                }
            }
        }
    }

    #pragma unroll
    for (int i = 0; i < 8; i++) atomicAdd(&DEN[lg + i], den[i]);
    __syncthreads();
    float* stage = (float*)smem;  // row-major [l][e], ld 68
    #pragma unroll
    for (int i = 0; i < 2; i++)
        #pragma unroll
        for (int j = 0; j < 2; j++)
            wmma::store_matrix_sync(stage + (warp_l + i*16)*68 + warp_e + j*16,
                                    c[i][j], 68, wmma::mem_row_major);
    __syncthreads();
    {
        int l = tid >> 1, ec = (tid & 1) * 32;
        float z = 1.0f / (DEN[l] + EPSZ);
        float* dst = out + ((size_t)((n*Ll + l0 + l)*Hh + h))*Ee + ec;
        const float* src = stage + l*68 + ec;
        #pragma unroll
        for (int j = 0; j < 8; j++) {
            float4 v = *(const float4*)(src + j*4);
            *(float4*)(dst + j*4) = make_float4(v.x*z, v.y*z, v.z*z, v.w*z);
        }
    }
}

// ================== launch ==================
extern "C" void kernel_launch(void* const* d_in, const int* in_sizes, int n_in,
                              void* d_out, int out_size)
{
    const float* q = (const float*)d_in[0];
    const float* k = (const float*)d_in[1];
    const float* v = (const float*)d_in[2];
    const float* p = (const float*)d_in[3];
    float* out = (float*)d_out;

    cudaFuncSetAttribute(k_feat, cudaFuncAttributeMaxDynamicSharedMemorySize, F_SMEM);
    cudaFuncSetAttribute(k_kv,   cudaFuncAttributeMaxDynamicSharedMemorySize, KV_SMEM);
    cudaFuncSetAttribute(k_out,  cudaFuncAttributeMaxDynamicSharedMemorySize, O_SMEM);

    k_init<<<8192, 256>>>(q, k);
    k_feat<<<dim3(16, 16, 32), 256, F_SMEM>>>(q, k, p);
    k_kv<<<dim3(16, HEADS), 256, KV_SMEM>>>(v);
    k_out<<<dim3(16, HEADS), 256, O_SMEM>>>(out);
}

// round 6
// speedup vs baseline: 1.1902x; 1.0364x over previous
#include <cuda_runtime.h>
#include <cuda_bf16.h>
#include <mma.h>
#include <math_constants.h>
#include <cstdint>

using namespace nvcuda;

#define Nn 2
#define Ll 2048
#define Hh 8
#define Ee 64
#define Mm 2048
#define HEADS 16
#define NLH (HEADS*Ll)

#define NRM   0.3535533905932738f
#define HNRM2 0.0625f
#define RATIO 0.022097086912079608f
#define KEPS  1e-4f
#define EPSZ  1e-6f

// ---------------- scratch ----------------
__device__ float g_Dq[(size_t)HEADS*Ll*Mm];
__device__ float g_Dk[(size_t)HEADS*Ll*Mm];
__device__ float g_rmax[2][NLH];
__device__ float g_diag[2][NLH];
__device__ __nv_bfloat16 g_Xhi[(size_t)2*HEADS*Ll*Ee];   // x*NRM split
__device__ __nv_bfloat16 g_Xlo[(size_t)2*HEADS*Ll*Ee];
__device__ __nv_bfloat16 g_Phi[(size_t)Mm*Ee];            // P split
__device__ __nv_bfloat16 g_Plo[(size_t)Mm*Ee];
__device__ __nv_bfloat16 g_VThi[(size_t)HEADS*Ee*Ll];    // v^T split [head][e][s]
__device__ __nv_bfloat16 g_VTlo[(size_t)HEADS*Ee*Ll];
__device__ __nv_bfloat16 g_Bhi[(size_t)HEADS*80*Mm];     // [head][80][m]: rows 0-63 kv^T, row 64 ksum
__device__ __nv_bfloat16 g_Blo[(size_t)HEADS*80*Mm];

__device__ __forceinline__ void atomicMaxF(float* addr, float v) {
    int* ia = (int*)addr;
    int old = *ia;
    while (__int_as_float(old) < v) {
        int assumed = old;
        old = atomicCAS(ia, assumed, __float_as_int(v));
        if (old == assumed) break;
    }
}

__device__ __forceinline__ void split1(float v, __nv_bfloat16& hi, __nv_bfloat16& lo) {
    hi = __float2bfloat16_rn(v);
    lo = __float2bfloat16_rn(v - __bfloat162float(hi));
}
__device__ __forceinline__ void split2pack(float a, float b, uint32_t& hi, uint32_t& lo) {
    __nv_bfloat16 ha, la, hb, lb;
    split1(a, ha, la); split1(b, hb, lb);
    __nv_bfloat162 H = __halves2bfloat162(ha, hb), L = __halves2bfloat162(la, lb);
    hi = *(uint32_t*)&H; lo = *(uint32_t*)&L;
}

__device__ __forceinline__ uint32_t smem_u32(const void* p) {
    uint32_t a;
    asm("{ .reg .u64 t; cvta.to.shared.u64 t, %1; cvt.u32.u64 %0, t; }" : "=r"(a) : "l"(p));
    return a;
}
__device__ __forceinline__ void cp16(uint32_t s, const void* g) {
    asm volatile("cp.async.cg.shared.global [%0], [%1], 16;" :: "r"(s), "l"(g));
}
#define CP_COMMIT() asm volatile("cp.async.commit_group;" ::: "memory")
#define CP_WAIT1()  asm volatile("cp.async.wait_group 1;" ::: "memory")
#define CP_WAIT0()  asm volatile("cp.async.wait_group 0;" ::: "memory")

typedef wmma::fragment<wmma::matrix_a, 16, 16, 16, __nv_bfloat16, wmma::row_major> FragA;
typedef wmma::fragment<wmma::matrix_b, 16, 16, 16, __nv_bfloat16, wmma::col_major> FragB;
typedef wmma::fragment<wmma::accumulator, 16, 16, 16, float> FragC;

// ================== K0: prep — diag/rmax + split X and P ==================
__global__ __launch_bounds__(256) void k_prep(const float* __restrict__ q,
                                              const float* __restrict__ kk,
                                              const float* __restrict__ P)
{
    int g = blockIdx.x * 256 + threadIdx.x;
    int w = g >> 5, lane = g & 31;
    if (w < 2*NLH) {
        int which = (w >= NLH) ? 1 : 0;
        int r = which ? (w - NLH) : w;
        int head = r >> 11, l = r & (Ll - 1);
        int n = head >> 3, h = head & 7;
        const float* x = (which ? kk : q) + ((size_t)((n*Ll + l)*Hh + h))*Ee;
        float2 f = *(const float2*)(x + 2*lane);
        float s = f.x*f.x + f.y*f.y;
        #pragma unroll
        for (int o = 16; o; o >>= 1) s += __shfl_xor_sync(0xffffffffu, s, o);
        if (lane == 0) {
            g_diag[which][r] = HNRM2 * s;
            g_rmax[which][r] = -CUDART_INF_F;
        }
        uint32_t hi, lo; split2pack(f.x*NRM, f.y*NRM, hi, lo);
        size_t base = ((size_t)(which*HEADS + head)*Ll + l)*Ee;
        *(uint32_t*)(g_Xhi + base + 2*lane) = hi;
        *(uint32_t*)(g_Xlo + base + 2*lane) = lo;
    } else {
        int m = w - 2*NLH;   // grid sized exactly: m in [0,2048)
        const float* p = P + (size_t)m*Ee;
        float2 f = *(const float2*)(p + 2*lane);
        uint32_t hi, lo; split2pack(f.x, f.y, hi, lo);
        *(uint32_t*)(g_Phi + (size_t)m*Ee + 2*lane) = hi;
        *(uint32_t*)(g_Plo + (size_t)m*Ee + 2*lane) = lo;
    }
}

// ================== K0b: v -> vT split [head][e][s] ==================
__global__ __launch_bounds__(256) void k_vt(const float* __restrict__ V)
{
    __shared__ __nv_bfloat16 sh[2][64][136];
    const int head = blockIdx.y, n = head >> 3, h = head & 7;
    const int s0 = blockIdx.x * 128;
    const int tid = threadIdx.x;

    {
        int s = tid >> 1, eh = (tid & 1) * 32;
        const float* vp = V + ((size_t)((n*Ll + s0 + s)*Hh + h))*Ee + eh;
        #pragma unroll
        for (int j = 0; j < 8; j++) {
            float4 f = *(const float4*)(vp + j*4);
            float vv[4] = {f.x, f.y, f.z, f.w};
            #pragma unroll
            for (int i = 0; i < 4; i++) {
                __nv_bfloat16 hb, lb; split1(vv[i], hb, lb);
                int e = eh + j*4 + i;
                sh[0][e][s] = hb;
                sh[1][e][s] = lb;
            }
        }
    }
    __syncthreads();
    {
        int e = tid >> 2, sc = (tid & 3) * 32;
        #pragma unroll
        for (int p = 0; p < 2; p++) {
            __nv_bfloat16* dst = (p ? g_VTlo : g_VThi) + ((size_t)(head*Ee + e))*Ll + s0 + sc;
            const uint32_t* src = (const uint32_t*)&sh[p][e][sc];
            #pragma unroll
            for (int i = 0; i < 16; i++) ((uint32_t*)dst)[i] = src[i];
        }
    }
}

// ================== K1: featurize (pure GEMM, cp.async) ==================
#define FK_LD 72
#define F_SMEM 73728
__global__ __launch_bounds__(256, 2) void k_feat()
{
    extern __shared__ char smem[];
    const uint32_t sb = smem_u32(smem);
    __nv_bfloat16* Ahi = (__nv_bfloat16*)(smem);
    __nv_bfloat16* Alo = (__nv_bfloat16*)(smem + 18432);
    __nv_bfloat16* Bhi = (__nv_bfloat16*)(smem + 36864);
    __nv_bfloat16* Blo = (__nv_bfloat16*)(smem + 55296);
    float* stage = (float*)smem;

    const int which = blockIdx.z >> 4;
    const int head = blockIdx.z & 15;
    float* __restrict__ Dash = which ? g_Dk : g_Dq;
    float* __restrict__ rmax = g_rmax[which];

    const int l0 = blockIdx.y * 128, m0 = blockIdx.x * 128;
    const int tid = threadIdx.x, wid = tid >> 5, lane = tid & 31;

    // cp.async fill: 4 planes x 128 rows x 8 chunks of 16B
    const __nv_bfloat16* baseA_hi = g_Xhi + ((size_t)(which*HEADS + head)*Ll + l0)*Ee;
    const __nv_bfloat16* baseA_lo = g_Xlo + ((size_t)(which*HEADS + head)*Ll + l0)*Ee;
    const __nv_bfloat16* baseB_hi = g_Phi + (size_t)m0*Ee;
    const __nv_bfloat16* baseB_lo = g_Plo + (size_t)m0*Ee;
    #pragma unroll
    for (int j = 0; j < 4; j++) {
        int g = tid + j*256, row = g >> 3, c = g & 7;
        cp16(sb + 0     + (row*FK_LD + c*8)*2, baseA_hi + row*Ee + c*8);
        cp16(sb + 18432 + (row*FK_LD + c*8)*2, baseA_lo + row*Ee + c*8);
        cp16(sb + 36864 + (row*FK_LD + c*8)*2, baseB_hi + row*Ee + c*8);
        cp16(sb + 55296 + (row*FK_LD + c*8)*2, baseB_lo + row*Ee + c*8);
    }
    CP_COMMIT();
    CP_WAIT0();
    __syncthreads();

    const int warp_l = (wid & 3) * 32, warp_m = (wid >> 2) * 64;
    FragC c[2][4];
    #pragma unroll
    for (int i = 0; i < 2; i++)
        #pragma unroll
        for (int j = 0; j < 4; j++) wmma::fill_fragment(c[i][j], 0.0f);

    #pragma unroll
    for (int k = 0; k < 4; k++) {
        FragA ahi[2], alo[2];
        #pragma unroll
        for (int i = 0; i < 2; i++) {
            wmma::load_matrix_sync(ahi[i], Ahi + (warp_l + i*16)*FK_LD + k*16, FK_LD);
            wmma::load_matrix_sync(alo[i], Alo + (warp_l + i*16)*FK_LD + k*16, FK_LD);
        }
        #pragma unroll
        for (int j = 0; j < 4; j++) {
            FragB bhi, blo;
            wmma::load_matrix_sync(bhi, Bhi + k*16 + (warp_m + j*16)*FK_LD, FK_LD);
            wmma::load_matrix_sync(blo, Blo + k*16 + (warp_m + j*16)*FK_LD, FK_LD);
            #pragma unroll
            for (int i = 0; i < 2; i++) {
                wmma::mma_sync(c[i][j], ahi[i], bhi, c[i][j]);
                wmma::mma_sync(c[i][j], ahi[i], blo, c[i][j]);
                wmma::mma_sync(c[i][j], alo[i], bhi, c[i][j]);
            }
        }
    }
    __syncthreads();
    #pragma unroll
    for (int i = 0; i < 2; i++)
        #pragma unroll
        for (int j = 0; j < 4; j++)
            wmma::store_matrix_sync(stage + (warp_l + i*16)*132 + warp_m + j*16,
                                    c[i][j], 132, wmma::mem_row_major);
    __syncthreads();

    #pragma unroll
    for (int r = 0; r < 16; r++) {
        int row = wid * 16 + r;
        float4 v = *(const float4*)&stage[row*132 + lane*4];
        *(float4*)(Dash + (size_t)(head*Ll + l0 + row)*Mm + m0 + lane*4) = v;
        float rm = fmaxf(fmaxf(v.x, v.y), fmaxf(v.z, v.w));
        #pragma unroll
        for (int o = 16; o; o >>= 1) rm = fmaxf(rm, __shfl_xor_sync(0xffffffffu, rm, o));
        if (lane == 0) atomicMaxF(&rmax[head*Ll + l0 + row], rm);
    }
}

// ================== K2: kv = k'^T @ v, writes split Bout + ksum row =======
// smem: rawK 2x16384 | Ah 10240 | Al 10240 | B 3x(5120+5120) | SUB 8192 | KS 512
#define KV_AH   32768
#define KV_AL   43008
#define KV_B    53248
#define KV_SUB  83968
#define KV_KS   92160
#define KV_SMEM 92672
__global__ __launch_bounds__(256, 2) void k_kv()
{
    extern __shared__ char smem[];
    const uint32_t sb = smem_u32(smem);
    __nv_bfloat16* Ah = (__nv_bfloat16*)(smem + KV_AH);
    __nv_bfloat16* Al = (__nv_bfloat16*)(smem + KV_AL);
    float* SUB = (float*)(smem + KV_SUB);
    float* KS  = (float*)(smem + KV_KS);

    const int head = blockIdx.y;
    const int m0 = blockIdx.x * 128;
    const int tid = threadIdx.x, wid = tid >> 5;

    // prologue: rawK + B operands for chunks 0,1
    #pragma unroll
    for (int t = 0; t < 2; t++) {
        const float* srcK = g_Dk + (size_t)(head*Ll + t*32)*Mm + m0;
        uint32_t dK = sb + t*16384;
        #pragma unroll
        for (int j = 0; j < 4; j++) {
            int g = tid + j*256, row = g >> 5, col = (g & 31)*4;
            cp16(dK + (row*128 + col)*4, srcK + (size_t)row*Mm + col);
        }
        // B: [64 e][32 s] hi+lo, ld 40
        {
            int g = tid, plane = g >> 8, q2 = g & 255, row = q2 >> 2, c = q2 & 3;
            const __nv_bfloat16* src = (plane ? g_VTlo : g_VThi)
                + (size_t)(head*Ee + row)*Ll + t*32 + c*8;
            cp16(sb + KV_B + t*10240 + plane*5120 + (row*40 + c*8)*2, src);
        }
        {
            int g = tid + 256, plane = g >> 8, q2 = g & 255, row = q2 >> 2, c = q2 & 3;
            const __nv_bfloat16* src = (plane ? g_VTlo : g_VThi)
                + (size_t)(head*Ee + row)*Ll + t*32 + c*8;
            cp16(sb + KV_B + t*10240 + plane*5120 + (row*40 + c*8)*2, src);
        }
        CP_COMMIT();
    }

    for (int i = tid; i < 2048; i += 256) {
        int gr = head*Ll + i;
        SUB[i] = g_diag[1][gr] + g_rmax[1][gr];
    }
    if (tid < 128) KS[tid] = 0.0f;

    const int mA = tid & 127, sgA = (tid >> 7) * 16;
    const int warp_m = (wid & 3) * 32, warp_e = (wid >> 2) * 32;

    FragC c[2][2];
    #pragma unroll
    for (int i = 0; i < 2; i++)
        #pragma unroll
        for (int j = 0; j < 2; j++) wmma::fill_fragment(c[i][j], 0.0f);

    float ksp = 0.0f;

    for (int t = 0; t < 64; t++) {
        if (t < 63) { CP_WAIT1(); } else { CP_WAIT0(); }
        __syncthreads();

        const float* RK = (const float*)(smem + (t & 1)*16384);

        #pragma unroll
        for (int i = 0; i < 16; i += 2) {
            float f0 = RK[(sgA + i)*128 + mA];
            float f1 = RK[(sgA + i + 1)*128 + mA];
            float k0 = RATIO * (__expf(f0 - SUB[t*32 + sgA + i])     + KEPS);
            float k1 = RATIO * (__expf(f1 - SUB[t*32 + sgA + i + 1]) + KEPS);
            ksp += k0 + k1;
            uint32_t hi, lo; split2pack(k0, k1, hi, lo);
            *(uint32_t*)&Ah[mA*40 + sgA + i] = hi;
            *(uint32_t*)&Al[mA*40 + sgA + i] = lo;
        }
        __syncthreads();

        if (t + 2 < 64) {
            const int s1 = (t + 2) * 32;
            const float* srcK = g_Dk + (size_t)(head*Ll + s1)*Mm + m0;
            uint32_t dK = sb + (t & 1)*16384;
            #pragma unroll
            for (int j = 0; j < 4; j++) {
                int g = tid + j*256, row = g >> 5, col = (g & 31)*4;
                cp16(dK + (row*128 + col)*4, srcK + (size_t)row*Mm + col);
            }
            uint32_t dB = sb + KV_B + ((t + 2) % 3)*10240;
            #pragma unroll
            for (int j = 0; j < 2; j++) {
                int g = tid + j*256, plane = g >> 8, q2 = g & 255, row = q2 >> 2, cc = q2 & 3;
                const __nv_bfloat16* src = (plane ? g_VTlo : g_VThi)
                    + (size_t)(head*Ee + row)*Ll + s1 + cc*8;
                cp16(dB + plane*5120 + (row*40 + cc*8)*2, src);
            }
            CP_COMMIT();
        }

        const __nv_bfloat16* Bh = (const __nv_bfloat16*)(smem + KV_B + (t % 3)*10240);
        const __nv_bfloat16* Bl = Bh + 2560;   // 5120 bytes

        #pragma unroll
        for (int k = 0; k < 2; k++) {
            FragA ahi[2], alo[2];
            #pragma unroll
            for (int i = 0; i < 2; i++) {
                wmma::load_matrix_sync(ahi[i], Ah + (warp_m + i*16)*40 + k*16, 40);
                wmma::load_matrix_sync(alo[i], Al + (warp_m + i*16)*40 + k*16, 40);
            }
            #pragma unroll
            for (int j = 0; j < 2; j++) {
                FragB bhi, blo;
                wmma::load_matrix_sync(bhi, Bh + (warp_e + j*16)*40 + k*16, 40);
                wmma::load_matrix_sync(blo, Bl + (warp_e + j*16)*40 + k*16, 40);
                #pragma unroll
                for (int i = 0; i < 2; i++) {
                    wmma::mma_sync(c[i][j], ahi[i], bhi, c[i][j]);
                    wmma::mma_sync(c[i][j], ahi[i], blo, c[i][j]);
                    wmma::mma_sync(c[i][j], alo[i], bhi, c[i][j]);
                }
            }
        }
    }

    atomicAdd(&KS[mA], ksp);
    __syncthreads();
    float* stage = (float*)smem;   // [e][m] via col_major store, ld 132
    #pragma unroll
    for (int i = 0; i < 2; i++)
        #pragma unroll
        for (int j = 0; j < 2; j++)
            wmma::store_matrix_sync(stage + (warp_m + i*16) + (warp_e + j*16)*132,
                                    c[i][j], 132, wmma::mem_col_major);
    __syncthreads();
    {
        int e = tid >> 2, mo = (tid & 3) * 32;
        const float* src = stage + e*132 + mo;
        __nv_bfloat16* dhi = g_Bhi + (size_t)(head*80 + e)*Mm + m0 + mo;
        __nv_bfloat16* dlo = g_Blo + (size_t)(head*80 + e)*Mm + m0 + mo;
        #pragma unroll
        for (int j = 0; j < 32; j += 2) {
            uint32_t hi, lo; split2pack(src[j], src[j+1], hi, lo);
            *(uint32_t*)(dhi + j) = hi;
            *(uint32_t*)(dlo + j) = lo;
        }
    }
    if (tid < 128) {
        __nv_bfloat16 hb, lb; split1(KS[tid], hb, lb);
        g_Bhi[(size_t)(head*80 + 64)*Mm + m0 + tid] = hb;
        g_Blo[(size_t)(head*80 + 64)*Mm + m0 + tid] = lb;
    }
}

// ================== K3: out = z * q' @ B^T (N=80: col 64 = denominator) ====
// smem: rawQ 2x18432 | Ah 10240 | Al 10240 | B 3x(6400+6400) | SUBL 512
#define O_AH    36864
#define O_AL    47104
#define O_B     57344
#define O_SUBL  95744
#define O_SMEM  96256
__global__ __launch_bounds__(256, 2) void k_out(float* __restrict__ out)
{
    extern __shared__ char smem[];
    const uint32_t sb = smem_u32(smem);
    __nv_bfloat16* Ah = (__nv_bfloat16*)(smem + O_AH);
    __nv_bfloat16* Al = (__nv_bfloat16*)(smem + O_AL);
    float* SUBL = (float*)(smem + O_SUBL);

    const int head = blockIdx.y, n = head >> 3, h = head & 7;
    const int l0 = blockIdx.x * 128;
    const int tid = threadIdx.x, wid = tid >> 5;

    // prologue for chunks 0,1
    #pragma unroll
    for (int t = 0; t < 2; t++) {
        const float* srcQ = g_Dq + (size_t)(head*Ll + l0)*Mm + t*32;
        uint32_t dQ = sb + t*18432;
        #pragma unroll
        for (int j = 0; j < 4; j++) {
            int g = tid + j*256, l = g >> 3, col = (g & 7)*4;
            cp16(dQ + (l*36 + col)*4, srcQ + (size_t)l*Mm + col);
        }
        uint32_t dB = sb + O_B + t*12800;
        #pragma unroll
        for (int j = 0; j < 3; j++) {
            int g = tid + j*256;
            if (g < 640) {
                int plane = g / 320, q2 = g % 320, row = q2 >> 2, cc = q2 & 3;
                const __nv_bfloat16* src = (plane ? g_Blo : g_Bhi)
                    + (size_t)(head*80 + row)*Mm + t*32 + cc*8;
                cp16(dB + plane*6400 + (row*40 + cc*8)*2, src);
            }
        }
        CP_COMMIT();
    }

    if (tid < 128) {
        int gr = head*Ll + l0 + tid;
        SUBL[tid] = g_diag[0][gr] + g_rmax[0][gr];
    }

    const int m2 = (tid & 15) * 2, lg = (tid >> 4) * 8;
    const int warp_l = wid * 16;

    FragC c[5];
    #pragma unroll
    for (int j = 0; j < 5; j++) wmma::fill_fragment(c[j], 0.0f);

    for (int t = 0; t < 64; t++) {
        if (t < 63) { CP_WAIT1(); } else { CP_WAIT0(); }
        __syncthreads();

        const float* RQ = (const float*)(smem + (t & 1)*18432);

        #pragma unroll
        for (int i = 0; i < 8; i++) {
            int l = lg + i;
            float2 f = *(const float2*)(RQ + l*36 + m2);
            float sub = SUBL[l];
            float q0 = RATIO * (__expf(f.x - sub) + KEPS);
            float q1 = RATIO * (__expf(f.y - sub) + KEPS);
            uint32_t hi, lo; split2pack(q0, q1, hi, lo);
            *(uint32_t*)&Ah[l*40 + m2] = hi;
            *(uint32_t*)&Al[l*40 + m2] = lo;
        }
        __syncthreads();

        if (t + 2 < 64) {
            const int m1 = (t + 2) * 32;
            const float* srcQ = g_Dq + (size_t)(head*Ll + l0)*Mm + m1;
            uint32_t dQ = sb + (t & 1)*18432;
            #pragma unroll
            for (int j = 0; j < 4; j++) {
                int g = tid + j*256, l = g >> 3, col = (g & 7)*4;
                cp16(dQ + (l*36 + col)*4, srcQ + (size_t)l*Mm + col);
            }
            uint32_t dB = sb + O_B + ((t + 2) % 3)*12800;
            #pragma unroll
            for (int j = 0; j < 3; j++) {
                int g = tid + j*256;
                if (g < 640) {
                    int plane = g / 320, q2 = g % 320, row = q2 >> 2, cc = q2 & 3;
                    const __nv_bfloat16* src = (plane ? g_Blo : g_Bhi)
                        + (size_t)(head*80 + row)*Mm + m1 + cc*8;
                    cp16(dB + plane*6400 + (row*40 + cc*8)*2, src);
                }
            }
            CP_COMMIT();
        }

        const __nv_bfloat16* Bh = (const __nv_bfloat16*)(smem + O_B + (t % 3)*12800);
        const __nv_bfloat16* Bl = Bh + 3200;   // 6400 bytes

        #pragma unroll
        for (int k = 0; k < 2; k++) {
            FragA ahi, alo;
            wmma::load_matrix_sync(ahi, Ah + warp_l*40 + k*16, 40);
            wmma::load_matrix_sync(alo, Al + warp_l*40 + k*16, 40);
            #pragma unroll
            for (int j = 0; j < 5; j++) {
                FragB bhi, blo;
                wmma::load_matrix_sync(bhi, Bh + (j*16)*40 + k*16, 40);
                wmma::load_matrix_sync(blo, Bl + (j*16)*40 + k*16, 40);
                wmma::mma_sync(c[j], ahi, bhi, c[j]);
                wmma::mma_sync(c[j], ahi, blo, c[j]);
                wmma::mma_sync(c[j], alo, bhi, c[j]);
            }
        }
    }

    __syncthreads();
    float* stage = (float*)smem;  // [l][84]
    #pragma unroll
    for (int j = 0; j < 5; j++)
        wmma::store_matrix_sync(stage + warp_l*84 + j*16, c[j], 84, wmma::mem_row_major);
    __syncthreads();
    {
        int l = tid >> 1, ec = (tid & 1) * 32;
        float z = 1.0f / (stage[l*84 + 64] + EPSZ);
        float* dst = out + ((size_t)((n*Ll + l0 + l)*Hh + h))*Ee + ec;
        const float* src = stage + l*84 + ec;
        #pragma unroll
        for (int j = 0; j < 8; j++) {
            float4 v = *(const float4*)(src + j*4);
            *(float4*)(dst + j*4) = make_float4(v.x*z, v.y*z, v.z*z, v.w*z);
        }
    }
}

// ================== launch ==================
extern "C" void kernel_launch(void* const* d_in, const int* in_sizes, int n_in,
                              void* d_out, int out_size)
{
    const float* q = (const float*)d_in[0];
    const float* k = (const float*)d_in[1];
    const float* v = (const float*)d_in[2];
    const float* p = (const float*)d_in[3];
    float* out = (float*)d_out;

    cudaFuncSetAttribute(k_feat, cudaFuncAttributeMaxDynamicSharedMemorySize, F_SMEM);
    cudaFuncSetAttribute(k_kv,   cudaFuncAttributeMaxDynamicSharedMemorySize, KV_SMEM);
    cudaFuncSetAttribute(k_out,  cudaFuncAttributeMaxDynamicSharedMemorySize, O_SMEM);

    k_prep<<<8448, 256>>>(q, k, p);
    k_vt<<<dim3(16, HEADS), 256>>>(v);
    k_feat<<<dim3(16, 16, 32), 256, F_SMEM>>>();
    k_kv<<<dim3(16, HEADS), 256, KV_SMEM>>>();
    k_out<<<dim3(16, HEADS), 256, O_SMEM>>>(out);
}

// round 8
// speedup vs baseline: 1.8676x; 1.5692x over previous
#include <cuda_runtime.h>
#include <cuda_bf16.h>
#include <mma.h>
#include <math_constants.h>
#include <cstdint>

using namespace nvcuda;

#define Nn 2
#define Ll 2048
#define Hh 8
#define Ee 64
#define Mm 2048
#define HEADS 16
#define NLH (HEADS*Ll)

#define NRM   0.3535533905932738f
#define HNRM2 0.0625f
#define RATIO 0.022097086912079608f
#define KEPS  1e-4f
#define EPSZ  1e-6f

// ---------------- scratch ----------------
__device__ float g_Dq[(size_t)HEADS*Ll*Mm];
__device__ float g_Dk[(size_t)HEADS*Ll*Mm];
__device__ float g_diag[2][NLH];
__device__ float g_pmax[(size_t)32*16*Ll];               // [wh][mtile][l]
__device__ float g_SUB[32*Ll];                            // diag + rowmax
__device__ __nv_bfloat16 g_Xhi[(size_t)2*HEADS*Ll*Ee];
__device__ __nv_bfloat16 g_Xlo[(size_t)2*HEADS*Ll*Ee];
__device__ __nv_bfloat16 g_Phi[(size_t)Mm*Ee];
__device__ __nv_bfloat16 g_Plo[(size_t)Mm*Ee];
__device__ __nv_bfloat16 g_VThi[(size_t)HEADS*Ee*Ll];
__device__ __nv_bfloat16 g_VTlo[(size_t)HEADS*Ee*Ll];
__device__ __nv_bfloat16 g_Bhi[(size_t)HEADS*80*Mm];     // rows 0-63 kv^T, row 64 ksum
__device__ __nv_bfloat16 g_Blo[(size_t)HEADS*80*Mm];

__device__ __forceinline__ void split1(float v, __nv_bfloat16& hi, __nv_bfloat16& lo) {
    hi = __float2bfloat16_rn(v);
    lo = __float2bfloat16_rn(v - __bfloat162float(hi));
}
__device__ __forceinline__ void split2pack(float a, float b, uint32_t& hi, uint32_t& lo) {
    __nv_bfloat16 ha, la, hb, lb;
    split1(a, ha, la); split1(b, hb, lb);
    __nv_bfloat162 H = __halves2bfloat162(ha, hb), L = __halves2bfloat162(la, lb);
    hi = *(uint32_t*)&H; lo = *(uint32_t*)&L;
}

__device__ __forceinline__ uint32_t smem_u32(const void* p) {
    uint32_t a;
    asm("{ .reg .u64 t; cvta.to.shared.u64 t, %1; cvt.u32.u64 %0, t; }" : "=r"(a) : "l"(p));
    return a;
}
__device__ __forceinline__ void cp16(uint32_t s, const void* g) {
    asm volatile("cp.async.cg.shared.global [%0], [%1], 16;" :: "r"(s), "l"(g));
}
#define CP_COMMIT() asm volatile("cp.async.commit_group;" ::: "memory")
#define CP_WAIT1()  asm volatile("cp.async.wait_group 1;" ::: "memory")
#define CP_WAIT0()  asm volatile("cp.async.wait_group 0;" ::: "memory")

typedef wmma::fragment<wmma::matrix_a, 16, 16, 16, __nv_bfloat16, wmma::row_major> FragA;
typedef wmma::fragment<wmma::matrix_b, 16, 16, 16, __nv_bfloat16, wmma::col_major> FragB;
typedef wmma::fragment<wmma::accumulator, 16, 16, 16, float> FragC;

// ================== K0: prep — diag + split X and P ==================
__global__ __launch_bounds__(256) void k_prep(const float* __restrict__ q,
                                              const float* __restrict__ kk,
                                              const float* __restrict__ P)
{
    int g = blockIdx.x * 256 + threadIdx.x;
    int w = g >> 5, lane = g & 31;
    if (w < 2*NLH) {
        int which = (w >= NLH) ? 1 : 0;
        int r = which ? (w - NLH) : w;
        int head = r >> 11, l = r & (Ll - 1);
        int n = head >> 3, h = head & 7;
        const float* x = (which ? kk : q) + ((size_t)((n*Ll + l)*Hh + h))*Ee;
        float2 f = *(const float2*)(x + 2*lane);
        float s = f.x*f.x + f.y*f.y;
        #pragma unroll
        for (int o = 16; o; o >>= 1) s += __shfl_xor_sync(0xffffffffu, s, o);
        if (lane == 0) g_diag[which][r] = HNRM2 * s;
        uint32_t hi, lo; split2pack(f.x*NRM, f.y*NRM, hi, lo);
        size_t base = ((size_t)(which*HEADS + head)*Ll + l)*Ee;
        *(uint32_t*)(g_Xhi + base + 2*lane) = hi;
        *(uint32_t*)(g_Xlo + base + 2*lane) = lo;
    } else {
        int m = w - 2*NLH;
        const float* p = P + (size_t)m*Ee;
        float2 f = *(const float2*)(p + 2*lane);
        uint32_t hi, lo; split2pack(f.x, f.y, hi, lo);
        *(uint32_t*)(g_Phi + (size_t)m*Ee + 2*lane) = hi;
        *(uint32_t*)(g_Plo + (size_t)m*Ee + 2*lane) = lo;
    }
}

// ================== K0b: v -> vT split ==================
__global__ __launch_bounds__(256) void k_vt(const float* __restrict__ V)
{
    __shared__ __nv_bfloat16 sh[2][64][136];
    const int head = blockIdx.y, n = head >> 3, h = head & 7;
    const int s0 = blockIdx.x * 128;
    const int tid = threadIdx.x;

    {
        int s = tid >> 1, eh = (tid & 1) * 32;
        const float* vp = V + ((size_t)((n*Ll + s0 + s)*Hh + h))*Ee + eh;
        #pragma unroll
        for (int j = 0; j < 8; j++) {
            float4 f = *(const float4*)(vp + j*4);
            float vv[4] = {f.x, f.y, f.z, f.w};
            #pragma unroll
            for (int i = 0; i < 4; i++) {
                __nv_bfloat16 hb, lb; split1(vv[i], hb, lb);
                int e = eh + j*4 + i;
                sh[0][e][s] = hb;
                sh[1][e][s] = lb;
            }
        }
    }
    __syncthreads();
    {
        int e = tid >> 2, sc = (tid & 3) * 32;
        #pragma unroll
        for (int p = 0; p < 2; p++) {
            __nv_bfloat16* dst = (p ? g_VTlo : g_VThi) + ((size_t)(head*Ee + e))*Ll + s0 + sc;
            const uint32_t* src = (const uint32_t*)&sh[p][e][sc];
            #pragma unroll
            for (int i = 0; i < 16; i++) ((uint32_t*)dst)[i] = src[i];
        }
    }
}

// ================== K1: featurize — persistent stripe, B resident ==========
// CTA: (mtile, lhalf, wh). 512 threads, 1 CTA/SM. Streams 8 l-tiles of 128.
// smem: Bhi/Blo 36864 | A 2x36864 | stage 128x132 f32 67584
#define FT_A     36864
#define FT_STG   110592
#define FT_SMEM  178176
__global__ __launch_bounds__(512, 1) void k_feat()
{
    extern __shared__ char smem[];
    const uint32_t sb = smem_u32(smem);
    const int wh = blockIdx.z;
    const int which = wh >> 4, head = wh & 15;
    const int m0 = blockIdx.x * 128;
    const int lbase = blockIdx.y * 1024;
    const int tid = threadIdx.x, wid = tid >> 5;
    float* __restrict__ Dash = which ? g_Dk : g_Dq;

    const __nv_bfloat16* Xhi = g_Xhi + (size_t)wh*Ll*Ee;
    const __nv_bfloat16* Xlo = g_Xlo + (size_t)wh*Ll*Ee;

    // prologue: B + A(tile0) -> G0 ; A(tile1) -> G1
    #pragma unroll
    for (int j = 0; j < 4; j++) {
        int g = tid + j*512;
        int plane = g >> 10, r = (g >> 3) & 127, c = g & 7;
        const __nv_bfloat16* src = (plane ? g_Plo : g_Phi) + (size_t)(m0 + r)*Ee + c*8;
        cp16(sb + plane*18432 + (r*72 + c*8)*2, src);
    }
    #pragma unroll
    for (int j = 0; j < 4; j++) {
        int g = tid + j*512;
        int plane = g >> 10, r = (g >> 3) & 127, c = g & 7;
        const __nv_bfloat16* src = (plane ? Xlo : Xhi) + (size_t)(lbase + r)*Ee + c*8;
        cp16(sb + FT_A + plane*18432 + (r*72 + c*8)*2, src);
    }
    CP_COMMIT();
    #pragma unroll
    for (int j = 0; j < 4; j++) {
        int g = tid + j*512;
        int plane = g >> 10, r = (g >> 3) & 127, c = g & 7;
        const __nv_bfloat16* src = (plane ? Xlo : Xhi) + (size_t)(lbase + 128 + r)*Ee + c*8;
        cp16(sb + FT_A + 36864 + plane*18432 + (r*72 + c*8)*2, src);
    }
    CP_COMMIT();

    const int warp_l = (wid & 3) * 32, warp_m = (wid >> 2) * 32;
    float* stage = (float*)(smem + FT_STG);
    const __nv_bfloat16* Bhi = (const __nv_bfloat16*)smem;
    const __nv_bfloat16* Blo = Bhi + 9216;

    for (int t = 0; t < 8; t++) {
        if (t < 7) { CP_WAIT1(); } else { CP_WAIT0(); }
        __syncthreads();   // A(t) + B visible to all; stage(t-1) reads done

        const __nv_bfloat16* Ahi = (const __nv_bfloat16*)(smem + FT_A + (t & 1)*36864);
        const __nv_bfloat16* Alo = Ahi + 9216;

        FragC c[2][2];
        #pragma unroll
        for (int i = 0; i < 2; i++)
            #pragma unroll
            for (int j = 0; j < 2; j++) wmma::fill_fragment(c[i][j], 0.0f);

        #pragma unroll
        for (int k = 0; k < 4; k++) {
            FragA ahi[2], alo[2];
            #pragma unroll
            for (int i = 0; i < 2; i++) {
                wmma::load_matrix_sync(ahi[i], Ahi + (warp_l + i*16)*72 + k*16, 72);
                wmma::load_matrix_sync(alo[i], Alo + (warp_l + i*16)*72 + k*16, 72);
            }
            #pragma unroll
            for (int j = 0; j < 2; j++) {
                FragB bhi, blo;
                wmma::load_matrix_sync(bhi, Bhi + (warp_m + j*16)*72 + k*16, 72);
                wmma::load_matrix_sync(blo, Blo + (warp_m + j*16)*72 + k*16, 72);
                #pragma unroll
                for (int i = 0; i < 2; i++) {
                    wmma::mma_sync(c[i][j], ahi[i], bhi, c[i][j]);
                    wmma::mma_sync(c[i][j], ahi[i], blo, c[i][j]);
                    wmma::mma_sync(c[i][j], alo[i], bhi, c[i][j]);
                }
            }
        }

        #pragma unroll
        for (int i = 0; i < 2; i++)
            #pragma unroll
            for (int j = 0; j < 2; j++)
                wmma::store_matrix_sync(stage + (warp_l + i*16)*132 + warp_m + j*16,
                                        c[i][j], 132, wmma::mem_row_major);
        __syncthreads();   // MMA reads of A(t) done; stage visible

        if (t + 2 < 8) {   // refill buf (t&1) for tile t+2 (A(t) fully consumed)
            #pragma unroll
            for (int j = 0; j < 4; j++) {
                int g = tid + j*512;
                int plane = g >> 10, r = (g >> 3) & 127, cc = g & 7;
                const __nv_bfloat16* src = (plane ? Xlo : Xhi)
                    + (size_t)(lbase + (t + 2)*128 + r)*Ee + cc*8;
                cp16(sb + FT_A + (t & 1)*36864 + plane*18432 + (r*72 + cc*8)*2, src);
            }
            CP_COMMIT();
        }

        // epilogue: coalesced store + partial rowmax (no atomics)
        {
            int row = tid >> 2;
            int l = lbase + t*128 + row;
            float rm = -CUDART_INF_F;
            float* dst = Dash + (size_t)(head*Ll + l)*Mm + m0;
            const float* srcr = stage + row*132;
            #pragma unroll
            for (int j = 0; j < 8; j++) {
                int col = (tid & 3)*4 + j*16;
                float4 v = *(const float4*)(srcr + col);
                rm = fmaxf(rm, fmaxf(fmaxf(v.x, v.y), fmaxf(v.z, v.w)));
                *(float4*)(dst + col) = v;
            }
            rm = fmaxf(rm, __shfl_xor_sync(0xffffffffu, rm, 1));
            rm = fmaxf(rm, __shfl_xor_sync(0xffffffffu, rm, 2));
            if ((tid & 3) == 0)
                g_pmax[((size_t)wh*16 + blockIdx.x)*Ll + l] = rm;
        }
    }
}

// ================== K1b: rowmax reduce + diag fold -> SUB ==================
__global__ __launch_bounds__(256) void k_rmax()
{
    int gw = (blockIdx.x * 256 + threadIdx.x) >> 5;   // 0..2047
    int lane = threadIdx.x & 31;
    int wh = gw >> 6;
    int l = (gw & 63) * 32 + lane;
    float m = -CUDART_INF_F;
    #pragma unroll
    for (int mt = 0; mt < 16; mt++)
        m = fmaxf(m, g_pmax[((size_t)wh*16 + mt)*Ll + l]);
    g_SUB[wh*Ll + l] = g_diag[wh >> 4][(wh & 15)*Ll + l] + m;
}

// ================== K2: kv (round-6 structure, SUB from g_SUB) ==========
#define KV_AH   32768
#define KV_AL   43008
#define KV_B    53248
#define KV_SUB  83968
#define KV_KS   92160
#define KV_SMEM 92672
__global__ __launch_bounds__(256, 2) void k_kv()
{
    extern __shared__ char smem[];
    const uint32_t sb = smem_u32(smem);
    __nv_bfloat16* Ah = (__nv_bfloat16*)(smem + KV_AH);
    __nv_bfloat16* Al = (__nv_bfloat16*)(smem + KV_AL);
    float* SUB = (float*)(smem + KV_SUB);
    float* KS  = (float*)(smem + KV_KS);

    const int head = blockIdx.y;
    const int m0 = blockIdx.x * 128;
    const int tid = threadIdx.x, wid = tid >> 5;

    #pragma unroll
    for (int t = 0; t < 2; t++) {
        const float* srcK = g_Dk + (size_t)(head*Ll + t*32)*Mm + m0;
        uint32_t dK = sb + t*16384;
        #pragma unroll
        for (int j = 0; j < 4; j++) {
            int g = tid + j*256, row = g >> 5, col = (g & 31)*4;
            cp16(dK + (row*128 + col)*4, srcK + (size_t)row*Mm + col);
        }
        uint32_t dB = sb + KV_B + t*10240;
        #pragma unroll
        for (int j = 0; j < 2; j++) {
            int g = tid + j*256, plane = g >> 8, q2 = g & 255, row = q2 >> 2, cc = q2 & 3;
            const __nv_bfloat16* src = (plane ? g_VTlo : g_VThi)
                + (size_t)(head*Ee + row)*Ll + t*32 + cc*8;
            cp16(dB + plane*5120 + (row*40 + cc*8)*2, src);
        }
        CP_COMMIT();
    }

    for (int i = tid; i < 2048; i += 256)
        SUB[i] = g_SUB[(16 + head)*Ll + i];
    if (tid < 128) KS[tid] = 0.0f;

    const int mA = tid & 127, sgA = (tid >> 7) * 16;
    const int warp_m = (wid & 3) * 32, warp_e = (wid >> 2) * 32;

    FragC c[2][2];
    #pragma unroll
    for (int i = 0; i < 2; i++)
        #pragma unroll
        for (int j = 0; j < 2; j++) wmma::fill_fragment(c[i][j], 0.0f);

    float ksp = 0.0f;

    for (int t = 0; t < 64; t++) {
        if (t < 63) { CP_WAIT1(); } else { CP_WAIT0(); }
        __syncthreads();

        const float* RK = (const float*)(smem + (t & 1)*16384);

        #pragma unroll
        for (int i = 0; i < 16; i += 2) {
            float f0 = RK[(sgA + i)*128 + mA];
            float f1 = RK[(sgA + i + 1)*128 + mA];
            float k0 = RATIO * (__expf(f0 - SUB[t*32 + sgA + i])     + KEPS);
            float k1 = RATIO * (__expf(f1 - SUB[t*32 + sgA + i + 1]) + KEPS);
            ksp += k0 + k1;
            uint32_t hi, lo; split2pack(k0, k1, hi, lo);
            *(uint32_t*)&Ah[mA*40 + sgA + i] = hi;
            *(uint32_t*)&Al[mA*40 + sgA + i] = lo;
        }
        __syncthreads();

        if (t + 2 < 64) {
            const int s1 = (t + 2) * 32;
            const float* srcK = g_Dk + (size_t)(head*Ll + s1)*Mm + m0;
            uint32_t dK = sb + (t & 1)*16384;
            #pragma unroll
            for (int j = 0; j < 4; j++) {
                int g = tid + j*256, row = g >> 5, col = (g & 31)*4;
                cp16(dK + (row*128 + col)*4, srcK + (size_t)row*Mm + col);
            }
            uint32_t dB = sb + KV_B + ((t + 2) % 3)*10240;
            #pragma unroll
            for (int j = 0; j < 2; j++) {
                int g = tid + j*256, plane = g >> 8, q2 = g & 255, row = q2 >> 2, cc = q2 & 3;
                const __nv_bfloat16* src = (plane ? g_VTlo : g_VThi)
                    + (size_t)(head*Ee + row)*Ll + s1 + cc*8;
                cp16(dB + plane*5120 + (row*40 + cc*8)*2, src);
            }
            CP_COMMIT();
        }

        const __nv_bfloat16* Bh = (const __nv_bfloat16*)(smem + KV_B + (t % 3)*10240);
        const __nv_bfloat16* Bl = Bh + 2560;

        #pragma unroll
        for (int k = 0; k < 2; k++) {
            FragA ahi[2], alo[2];
            #pragma unroll
            for (int i = 0; i < 2; i++) {
                wmma::load_matrix_sync(ahi[i], Ah + (warp_m + i*16)*40 + k*16, 40);
                wmma::load_matrix_sync(alo[i], Al + (warp_m + i*16)*40 + k*16, 40);
            }
            #pragma unroll
            for (int j = 0; j < 2; j++) {
                FragB bhi, blo;
                wmma::load_matrix_sync(bhi, Bh + (warp_e + j*16)*40 + k*16, 40);
                wmma::load_matrix_sync(blo, Bl + (warp_e + j*16)*40 + k*16, 40);
                #pragma unroll
                for (int i = 0; i < 2; i++) {
                    wmma::mma_sync(c[i][j], ahi[i], bhi, c[i][j]);
                    wmma::mma_sync(c[i][j], ahi[i], blo, c[i][j]);
                    wmma::mma_sync(c[i][j], alo[i], bhi, c[i][j]);
                }
            }
        }
    }

    atomicAdd(&KS[mA], ksp);
    __syncthreads();
    float* stage = (float*)smem;
    #pragma unroll
    for (int i = 0; i < 2; i++)
        #pragma unroll
        for (int j = 0; j < 2; j++)
            wmma::store_matrix_sync(stage + (warp_m + i*16) + (warp_e + j*16)*132,
                                    c[i][j], 132, wmma::mem_col_major);
    __syncthreads();
    {
        int e = tid >> 2, mo = (tid & 3) * 32;
        const float* src = stage + e*132 + mo;
        __nv_bfloat16* dhi = g_Bhi + (size_t)(head*80 + e)*Mm + m0 + mo;
        __nv_bfloat16* dlo = g_Blo + (size_t)(head*80 + e)*Mm + m0 + mo;
        #pragma unroll
        for (int j = 0; j < 32; j += 2) {
            uint32_t hi, lo; split2pack(src[j], src[j+1], hi, lo);
            *(uint32_t*)(dhi + j) = hi;
            *(uint32_t*)(dlo + j) = lo;
        }
    }
    if (tid < 128) {
        __nv_bfloat16 hb, lb; split1(KS[tid], hb, lb);
        g_Bhi[(size_t)(head*80 + 64)*Mm + m0 + tid] = hb;
        g_Blo[(size_t)(head*80 + 64)*Mm + m0 + tid] = lb;
    }
}

// ================== K3: out (round-6 structure, N=80 incl. denominator) ====
#define O_AH    36864
#define O_AL    47104
#define O_B     57344
#define O_SUBL  95744
#define O_SMEM  96256
__global__ __launch_bounds__(256, 2) void k_out(float* __restrict__ out)
{
    extern __shared__ char smem[];
    const uint32_t sb = smem_u32(smem);
    __nv_bfloat16* Ah = (__nv_bfloat16*)(smem + O_AH);
    __nv_bfloat16* Al = (__nv_bfloat16*)(smem + O_AL);
    float* SUBL = (float*)(smem + O_SUBL);

    const int head = blockIdx.y, n = head >> 3, h = head & 7;
    const int l0 = blockIdx.x * 128;
    const int tid = threadIdx.x, wid = tid >> 5;

    #pragma unroll
    for (int t = 0; t < 2; t++) {
        const float* srcQ = g_Dq + (size_t)(head*Ll + l0)*Mm + t*32;
        uint32_t dQ = sb + t*18432;
        #pragma unroll
        for (int j = 0; j < 4; j++) {
            int g = tid + j*256, l = g >> 3, col = (g & 7)*4;
            cp16(dQ + (l*36 + col)*4, srcQ + (size_t)l*Mm + col);
        }
        uint32_t dB = sb + O_B + t*12800;
        #pragma unroll
        for (int j = 0; j < 3; j++) {
            int g = tid + j*256;
            if (g < 640) {
                int plane = g / 320, q2 = g % 320, row = q2 >> 2, cc = q2 & 3;
                const __nv_bfloat16* src = (plane ? g_Blo : g_Bhi)
                    + (size_t)(head*80 + row)*Mm + t*32 + cc*8;
                cp16(dB + plane*6400 + (row*40 + cc*8)*2, src);
            }
        }
        CP_COMMIT();
    }

    if (tid < 128)
        SUBL[tid] = g_SUB[head*Ll + l0 + tid];

    const int m2 = (tid & 15) * 2, lg = (tid >> 4) * 8;
    const int warp_l = wid * 16;

    FragC c[5];
    #pragma unroll
    for (int j = 0; j < 5; j++) wmma::fill_fragment(c[j], 0.0f);

    for (int t = 0; t < 64; t++) {
        if (t < 63) { CP_WAIT1(); } else { CP_WAIT0(); }
        __syncthreads();

        const float* RQ = (const float*)(smem + (t & 1)*18432);

        #pragma unroll
        for (int i = 0; i < 8; i++) {
            int l = lg + i;
            float2 f = *(const float2*)(RQ + l*36 + m2);
            float sub = SUBL[l];
            float q0 = RATIO * (__expf(f.x - sub) + KEPS);
            float q1 = RATIO * (__expf(f.y - sub) + KEPS);
            uint32_t hi, lo; split2pack(q0, q1, hi, lo);
            *(uint32_t*)&Ah[l*40 + m2] = hi;
            *(uint32_t*)&Al[l*40 + m2] = lo;
        }
        __syncthreads();

        if (t + 2 < 64) {
            const int m1 = (t + 2) * 32;
            const float* srcQ = g_Dq + (size_t)(head*Ll + l0)*Mm + m1;
            uint32_t dQ = sb + (t & 1)*18432;
            #pragma unroll
            for (int j = 0; j < 4; j++) {
                int g = tid + j*256, l = g >> 3, col = (g & 7)*4;
                cp16(dQ + (l*36 + col)*4, srcQ + (size_t)l*Mm + col);
            }
            uint32_t dB = sb + O_B + ((t + 2) % 3)*12800;
            #pragma unroll
            for (int j = 0; j < 3; j++) {
                int g = tid + j*256;
                if (g < 640) {
                    int plane = g / 320, q2 = g % 320, row = q2 >> 2, cc = q2 & 3;
                    const __nv_bfloat16* src = (plane ? g_Blo : g_Bhi)
                        + (size_t)(head*80 + row)*Mm + m1 + cc*8;
                    cp16(dB + plane*6400 + (row*40 + cc*8)*2, src);
                }
            }
            CP_COMMIT();
        }

        const __nv_bfloat16* Bh = (const __nv_bfloat16*)(smem + O_B + (t % 3)*12800);
        const __nv_bfloat16* Bl = Bh + 3200;

        #pragma unroll
        for (int k = 0; k < 2; k++) {
            FragA ahi, alo;
            wmma::load_matrix_sync(ahi, Ah + warp_l*40 + k*16, 40);
            wmma::load_matrix_sync(alo, Al + warp_l*40 + k*16, 40);
            #pragma unroll
            for (int j = 0; j < 5; j++) {
                FragB bhi, blo;
                wmma::load_matrix_sync(bhi, Bh + (j*16)*40 + k*16, 40);
                wmma::load_matrix_sync(blo, Bl + (j*16)*40 + k*16, 40);
                wmma::mma_sync(c[j], ahi, bhi, c[j]);
                wmma::mma_sync(c[j], ahi, blo, c[j]);
                wmma::mma_sync(c[j], alo, bhi, c[j]);
            }
        }
    }

    __syncthreads();
    float* stage = (float*)smem;  // [l][84]
    #pragma unroll
    for (int j = 0; j < 5; j++)
        wmma::store_matrix_sync(stage + warp_l*84 + j*16, c[j], 84, wmma::mem_row_major);
    __syncthreads();
    {
        int l = tid >> 1, ec = (tid & 1) * 32;
        float z = 1.0f / (stage[l*84 + 64] + EPSZ);
        float* dst = out + ((size_t)((n*Ll + l0 + l)*Hh + h))*Ee + ec;
        const float* src = stage + l*84 + ec;
        #pragma unroll
        for (int j = 0; j < 8; j++) {
            float4 v = *(const float4*)(src + j*4);
            *(float4*)(dst + j*4) = make_float4(v.x*z, v.y*z, v.z*z, v.w*z);
        }
    }
}

// ================== launch ==================
extern "C" void kernel_launch(void* const* d_in, const int* in_sizes, int n_in,
                              void* d_out, int out_size)
{
    const float* q = (const float*)d_in[0];
    const float* k = (const float*)d_in[1];
    const float* v = (const float*)d_in[2];
    const float* p = (const float*)d_in[3];
    float* out = (float*)d_out;

    cudaFuncSetAttribute(k_feat, cudaFuncAttributeMaxDynamicSharedMemorySize, FT_SMEM);
    cudaFuncSetAttribute(k_kv,   cudaFuncAttributeMaxDynamicSharedMemorySize, KV_SMEM);
    cudaFuncSetAttribute(k_out,  cudaFuncAttributeMaxDynamicSharedMemorySize, O_SMEM);

    k_prep<<<8448, 256>>>(q, k, p);
    k_vt<<<dim3(16, HEADS), 256>>>(v);
    k_feat<<<dim3(16, 2, 32), 512, FT_SMEM>>>();
    k_rmax<<<256, 256>>>();
    k_kv<<<dim3(16, HEADS), 256, KV_SMEM>>>();
    k_out<<<dim3(16, HEADS), 256, O_SMEM>>>(out);
}